// round 2
// baseline (speedup 1.0000x reference)
#include <cuda_runtime.h>

typedef unsigned long long ull;

// ---------------- packed f32x2 PTX helpers ----------------
__device__ __forceinline__ ull pack2(float lo, float hi) {
    ull r; asm("mov.b64 %0, {%1, %2};" : "=l"(r) : "f"(lo), "f"(hi)); return r;
}
__device__ __forceinline__ void unpack2(ull v, float& lo, float& hi) {
    asm("mov.b64 {%0, %1}, %2;" : "=f"(lo), "=f"(hi) : "l"(v));
}
__device__ __forceinline__ void fma2(ull& d, ull a, ull b) {
    asm("fma.rn.f32x2 %0, %1, %2, %0;" : "+l"(d) : "l"(a), "l"(b));
}
__device__ __forceinline__ ull mul2(ull a, ull b) {
    ull d; asm("mul.rn.f32x2 %0, %1, %2;" : "=l"(d) : "l"(a), "l"(b)); return d;
}
__device__ __forceinline__ void add2(ull& d, ull a) {
    asm("add.rn.f32x2 %0, %0, %1;" : "+l"(d) : "l"(a));
}

// ---------------- problem constants ----------------
#define Bn   16
#define Nn   2048
#define DIN  512
#define DK   10
#define NH   2
#define DH   5
#define HID  20
#define DOUT 512
#define BH   (Bn * NH)          // 32
#define ROWS (Bn * Nn)          // 32768

// ---------------- device scratch ----------------
__device__ float g_Q[BH][Nn][8];   // Q pre-scaled by 1/sqrt(5)
__device__ float g_K[BH][Nn][8];
__device__ float g_V[BH][Nn][8];
__device__ float g_C[ROWS][DK];    // attention output [row][h*5+d]

// =====================================================================
// Kernel 1: fused QKV projection, f32x2 packed over column pairs.
// 128 threads = 128 rows, 1 row/thread, 30 cols = 15 packed accumulators.
// xs stored [row][k] with stride 65 -> conflict-free scalar LDS.
// ws[k][32] broadcast float4 reads.
// =====================================================================
#define PR   128
#define PKC  64
#define XPAD 65

__global__ __launch_bounds__(128) void proj_kernel(
    const float* __restrict__ x,
    const float* __restrict__ Wq, const float* __restrict__ bq,
    const float* __restrict__ Wk, const float* __restrict__ bk,
    const float* __restrict__ Wv, const float* __restrict__ bv)
{
    __shared__ float xs[PR * XPAD];                 // 33.3 KB
    __shared__ __align__(16) float ws[PKC * 32];    // 8 KB

    const int tid  = threadIdx.x;                   // = row within block
    const int row0 = blockIdx.x * PR;

    ull acc[15];
#pragma unroll
    for (int i = 0; i < 15; i++) acc[i] = 0ull;

    for (int kc = 0; kc < DIN; kc += PKC) {
        __syncthreads();
        // x tile: 128 rows x 64 cols, coalesced float4 reads, scalar STS
        for (int e = tid; e < PR * PKC / 4; e += 128) {
            int r  = e >> 4;
            int c4 = e & 15;
            float4 v = *reinterpret_cast<const float4*>(
                x + (size_t)(row0 + r) * DIN + kc + c4 * 4);
            float* p = xs + r * XPAD + c4 * 4;
            p[0] = v.x; p[1] = v.y; p[2] = v.z; p[3] = v.w;
        }
        // W tile: 64 k x 30 cols (Wq|Wk|Wv)
        for (int e = tid; e < PKC * 30; e += 128) {
            int k = e / 30, j = e % 30;
            float w;
            if (j < 10)      w = Wq[(kc + k) * DK + j];
            else if (j < 20) w = Wk[(kc + k) * DK + (j - 10)];
            else             w = Wv[(kc + k) * DK + (j - 20)];
            ws[k * 32 + j] = w;
        }
        __syncthreads();

#pragma unroll 8
        for (int k = 0; k < PKC; k++) {
            float xk = xs[tid * XPAD + k];
            ull  xp = pack2(xk, xk);
            const float4* w4 = reinterpret_cast<const float4*>(ws + k * 32);
#pragma unroll
            for (int i = 0; i < 7; i++) {
                float4 w = w4[i];
                union { float2 f; ull u; } a, b;
                a.f = make_float2(w.x, w.y);
                b.f = make_float2(w.z, w.w);
                fma2(acc[2 * i],     xp, a.u);
                fma2(acc[2 * i + 1], xp, b.u);
            }
            {   // pair 14 = cols 28,29
                union { float2 f; ull u; } c;
                c.f = *reinterpret_cast<const float2*>(ws + k * 32 + 28);
                fma2(acc[14], xp, c.u);
            }
        }
    }

    // epilogue: unpack, bias, scatter head-major
    float o[30];
#pragma unroll
    for (int i = 0; i < 15; i++) unpack2(acc[i], o[2 * i], o[2 * i + 1]);

    const int grow = row0 + tid;
    const int b = grow >> 11, n = grow & (Nn - 1);
    const float rs = 0.4472135954999579f;   // 1/sqrt(5)

    float q[10], kk[10], vv[10];
#pragma unroll
    for (int j = 0; j < 10; j++) {
        q[j]  = (o[j]      + bq[j]) * rs;
        kk[j] = (o[j + 10] + bk[j]);
        vv[j] = (o[j + 20] + bv[j]);
    }
#pragma unroll
    for (int h = 0; h < 2; h++) {
        int bh = b * NH + h;
        float* qp = g_Q[bh][n];
        float* kp = g_K[bh][n];
        float* vp = g_V[bh][n];
        *reinterpret_cast<float4*>(qp) = make_float4(q[h*5+0], q[h*5+1], q[h*5+2], q[h*5+3]);
        qp[4] = q[h*5+4];
        *reinterpret_cast<float4*>(kp) = make_float4(kk[h*5+0], kk[h*5+1], kk[h*5+2], kk[h*5+3]);
        kp[4] = kk[h*5+4];
        *reinterpret_cast<float4*>(vp) = make_float4(vv[h*5+0], vv[h*5+1], vv[h*5+2], vv[h*5+3]);
        vp[4] = vv[h*5+4];
    }
}

// =====================================================================
// Kernel 2: streaming causal attention, f32x2 packed over KEY PAIRS.
// smem K/V transposed: sK[d*128 + j] so an LDS.64 at (d, pair p) yields the
// packed (K[2p][d], K[2p+1][d]). sin in [-1,1] => weight=exp(sin(.)), no max.
// MUFU (SIN+EX2) is the binding pipe; all FFMA packed.
// =====================================================================
#define TK 128

template <bool DIAG>
__device__ __forceinline__ void attn_tile(
    const float* __restrict__ sK, const float* __restrict__ sV,
    const ull* __restrict__ q2, int lim,
    ull acc2[5], ull& den2)
{
    const ull* K2 = reinterpret_cast<const ull*>(sK);   // [d*64 + p]
    const ull* V2 = reinterpret_cast<const ull*>(sV);
#pragma unroll 4
    for (int p = 0; p < TK / 2; p++) {
        ull s2 = mul2(q2[4], K2[4 * 64 + p]);
        fma2(s2, q2[0], K2[0 * 64 + p]);
        fma2(s2, q2[1], K2[1 * 64 + p]);
        fma2(s2, q2[2], K2[2 * 64 + p]);
        fma2(s2, q2[3], K2[3 * 64 + p]);
        float s0, s1; unpack2(s2, s0, s1);
        float e0 = __expf(__sinf(s0));
        float e1 = __expf(__sinf(s1));
        if (DIAG) {
            e0 = (2 * p     <= lim) ? e0 : 0.f;
            e1 = (2 * p + 1 <= lim) ? e1 : 0.f;
        }
        ull e2 = pack2(e0, e1);
        add2(den2, e2);
        fma2(acc2[0], e2, V2[0 * 64 + p]);
        fma2(acc2[1], e2, V2[1 * 64 + p]);
        fma2(acc2[2], e2, V2[2 * 64 + p]);
        fma2(acc2[3], e2, V2[3 * 64 + p]);
        fma2(acc2[4], e2, V2[4 * 64 + p]);
    }
}

__global__ __launch_bounds__(128) void attn_kernel()
{
    __shared__ __align__(16) float sK[5 * TK];
    __shared__ __align__(16) float sV[5 * TK];

    const int tid = threadIdx.x;
    const int qt  = (gridDim.x - 1) - blockIdx.x;   // heavy tiles first
    const int bh  = blockIdx.y;
    const int qi  = qt * TK + tid;

    const float* qp = g_Q[bh][qi];
    float4 qv = *reinterpret_cast<const float4*>(qp);
    float  q4 = qp[4];
    ull q2[5];
    q2[0] = pack2(qv.x, qv.x); q2[1] = pack2(qv.y, qv.y);
    q2[2] = pack2(qv.z, qv.z); q2[3] = pack2(qv.w, qv.w);
    q2[4] = pack2(q4, q4);

    ull acc2[5] = {0ull, 0ull, 0ull, 0ull, 0ull};
    ull den2 = 0ull;

    for (int kt = 0; kt <= qt; kt++) {
        const int j = kt * TK + tid;
        const float* kp = g_K[bh][j];
        const float* vp = g_V[bh][j];
        float4 ka = *reinterpret_cast<const float4*>(kp);
        float  k4 = kp[4];
        float4 va = *reinterpret_cast<const float4*>(vp);
        float  v4 = vp[4];
        __syncthreads();
        sK[0 * TK + tid] = ka.x; sK[1 * TK + tid] = ka.y;
        sK[2 * TK + tid] = ka.z; sK[3 * TK + tid] = ka.w;
        sK[4 * TK + tid] = k4;
        sV[0 * TK + tid] = va.x; sV[1 * TK + tid] = va.y;
        sV[2 * TK + tid] = va.z; sV[3 * TK + tid] = va.w;
        sV[4 * TK + tid] = v4;
        __syncthreads();

        if (kt < qt) attn_tile<false>(sK, sV, q2, 0,   acc2, den2);
        else         attn_tile<true >(sK, sV, q2, tid, acc2, den2);
    }

    float dl, dh; unpack2(den2, dl, dh);
    const float inv = __fdividef(1.f, dl + dh);
    const int b = bh >> 1, h = bh & 1;
    float* op = &g_C[(size_t)b * Nn + qi][h * DH];
#pragma unroll
    for (int d = 0; d < 5; d++) {
        float al, ah; unpack2(acc2[d], al, ah);
        op[d] = (al + ah) * inv;
    }
}

// =====================================================================
// Kernel 3: MLP head, f32x2 packed over output-column pairs.
// 256 threads / 32 rows per block; Wm2 staged in smem (40KB); h packed
// (h_k,h_k) in registers; all Wm2 LDS conflict-free multicast.
// =====================================================================
#define MR 32

__global__ __launch_bounds__(256) void mlp_kernel(
    const float* __restrict__ Wm1, const float* __restrict__ bm1,
    const float* __restrict__ Wm2, const float* __restrict__ bm2,
    float* __restrict__ out)
{
    __shared__ __align__(16) float w2s[HID * DOUT];  // 40 KB
    __shared__ __align__(16) float h1s[MR * HID];

    const int tid  = threadIdx.x;
    const int row0 = blockIdx.x * MR;

    for (int e = tid; e < HID * DOUT / 4; e += 256)
        reinterpret_cast<float4*>(w2s)[e] = reinterpret_cast<const float4*>(Wm2)[e];

    for (int e = tid; e < MR * HID; e += 256) {
        int r = e / HID, j = e % HID;
        const float* crow = g_C[row0 + r];
        float s = bm1[j];
#pragma unroll
        for (int k = 0; k < DK; k++)
            s = fmaf(crow[k], Wm1[k * HID + j], s);
        h1s[e] = (s > 0.f) ? s : 0.01f * s;
    }
    __syncthreads();

    const int r  = tid >> 3;   // 0..31
    const int cg = tid & 7;    // 0..7
    ull h2[HID];
#pragma unroll
    for (int k = 0; k < HID; k++) {
        float hk = h1s[r * HID + k];
        h2[k] = pack2(hk, hk);
    }

    float* orow = out + (size_t)(row0 + r) * DOUT;
#pragma unroll 2
    for (int c4 = cg; c4 < DOUT / 4; c4 += 8) {
        union { float4 f; ull u[2]; } a;
        a.f = reinterpret_cast<const float4*>(bm2)[c4];
#pragma unroll
        for (int k = 0; k < HID; k++) {
            union { float4 f; ull u[2]; } w;
            w.f = *reinterpret_cast<const float4*>(w2s + k * DOUT + c4 * 4);
            fma2(a.u[0], h2[k], w.u[0]);
            fma2(a.u[1], h2[k], w.u[1]);
        }
        reinterpret_cast<float4*>(orow)[c4] = a.f;
    }
}

// =====================================================================
extern "C" void kernel_launch(void* const* d_in, const int* in_sizes, int n_in,
                              void* d_out, int out_size)
{
    const float* x   = (const float*)d_in[0];
    const float* Wq  = (const float*)d_in[1];
    const float* bq  = (const float*)d_in[2];
    const float* Wk  = (const float*)d_in[3];
    const float* bk  = (const float*)d_in[4];
    const float* Wv  = (const float*)d_in[5];
    const float* bv  = (const float*)d_in[6];
    const float* Wm1 = (const float*)d_in[7];
    const float* bm1 = (const float*)d_in[8];
    const float* Wm2 = (const float*)d_in[9];
    const float* bm2 = (const float*)d_in[10];

    proj_kernel<<<ROWS / PR, 128>>>(x, Wq, bq, Wk, bk, Wv, bv);
    attn_kernel<<<dim3(Nn / TK, BH), 128>>>();
    mlp_kernel<<<ROWS / MR, 256>>>(Wm1, bm1, Wm2, bm2, (float*)d_out);
}

// round 3
// speedup vs baseline: 1.2342x; 1.2342x over previous
#include <cuda_runtime.h>

typedef unsigned long long ull;

// ---------------- packed f32x2 PTX helpers ----------------
__device__ __forceinline__ ull pack2(float lo, float hi) {
    ull r; asm("mov.b64 %0, {%1, %2};" : "=l"(r) : "f"(lo), "f"(hi)); return r;
}
__device__ __forceinline__ void unpack2(ull v, float& lo, float& hi) {
    asm("mov.b64 {%0, %1}, %2;" : "=f"(lo), "=f"(hi) : "l"(v));
}
__device__ __forceinline__ void fma2(ull& d, ull a, ull b) {
    asm("fma.rn.f32x2 %0, %1, %2, %0;" : "+l"(d) : "l"(a), "l"(b));
}
__device__ __forceinline__ ull mul2(ull a, ull b) {
    ull d; asm("mul.rn.f32x2 %0, %1, %2;" : "=l"(d) : "l"(a), "l"(b)); return d;
}
__device__ __forceinline__ void add2(ull& d, ull a) {
    asm("add.rn.f32x2 %0, %0, %1;" : "+l"(d) : "l"(a));
}

// ---------------- problem constants ----------------
#define Bn   16
#define Nn   2048
#define DIN  512
#define DK   10
#define NH   2
#define DH   5
#define HID  20
#define DOUT 512
#define BH   (Bn * NH)          // 32
#define ROWS (Bn * Nn)          // 32768

// ---------------- device scratch ----------------
__device__ float g_Q[BH][Nn][8];       // Q pre-scaled by 1/sqrt(5)
__device__ float g_K[BH][Nn][8];
__device__ float g_V[BH][Nn][8];
// attention partials per key-half: [bh][q][khalf][ a0..a4, den, pad, pad ]
__device__ float g_A[BH][Nn][2][8];

// =====================================================================
// Kernel 1: fused QKV projection.
// 256 threads = 128 rows x 2 k-halves. Each thread: its row, half of each
// staged 64-k chunk (32 k), 15 packed f32x2 accumulators over 30 cols.
// Partial sums combined through smem at the end; khalf 0 does epilogue.
// =====================================================================
#define PR   128
#define PKC  64
#define XPAD 65

__global__ __launch_bounds__(256) void proj_kernel(
    const float* __restrict__ x,
    const float* __restrict__ Wq, const float* __restrict__ bq,
    const float* __restrict__ Wk, const float* __restrict__ bk,
    const float* __restrict__ Wv, const float* __restrict__ bv)
{
    __shared__ float xs[PR * XPAD];                 // 33.3 KB
    __shared__ __align__(16) float ws[PKC * 32];    // 8 KB

    const int tid  = threadIdx.x;
    const int row  = tid & 127;
    const int kh   = tid >> 7;        // 0 or 1: which half of each chunk
    const int row0 = blockIdx.x * PR;

    ull acc[15];
#pragma unroll
    for (int i = 0; i < 15; i++) acc[i] = 0ull;

    for (int kc = 0; kc < DIN; kc += PKC) {
        __syncthreads();
        // stage x tile: 128 rows x 64 cols, coalesced float4 reads
        for (int e = tid; e < PR * PKC / 4; e += 256) {
            int r  = e >> 4;
            int c4 = e & 15;
            float4 v = *reinterpret_cast<const float4*>(
                x + (size_t)(row0 + r) * DIN + kc + c4 * 4);
            float* p = xs + r * XPAD + c4 * 4;
            p[0] = v.x; p[1] = v.y; p[2] = v.z; p[3] = v.w;
        }
        // stage W tile: 64 k x 30 cols (Wq|Wk|Wv)
        for (int e = tid; e < PKC * 30; e += 256) {
            int k = e / 30, j = e % 30;
            float w;
            if (j < 10)      w = Wq[(kc + k) * DK + j];
            else if (j < 20) w = Wk[(kc + k) * DK + (j - 10)];
            else             w = Wv[(kc + k) * DK + (j - 20)];
            ws[k * 32 + j] = w;
        }
        __syncthreads();

        const float* xrow = xs + row * XPAD + kh * 32;
        const float* wbase = ws + (kh * 32) * 32;
#pragma unroll 8
        for (int k = 0; k < 32; k++) {
            float xk = xrow[k];
            ull  xp = pack2(xk, xk);
            const float4* w4 = reinterpret_cast<const float4*>(wbase + k * 32);
#pragma unroll
            for (int i = 0; i < 7; i++) {
                float4 w = w4[i];
                union { float2 f; ull u; } a, b;
                a.f = make_float2(w.x, w.y);
                b.f = make_float2(w.z, w.w);
                fma2(acc[2 * i],     xp, a.u);
                fma2(acc[2 * i + 1], xp, b.u);
            }
            {
                union { float2 f; ull u; } c;
                c.f = *reinterpret_cast<const float2*>(wbase + k * 32 + 28);
                fma2(acc[14], xp, c.u);
            }
        }
    }

    // ---- combine the two k-halves through smem ----
    __syncthreads();
    if (kh == 1) {
        float* dst = xs + row * 30;
#pragma unroll
        for (int i = 0; i < 15; i++) {
            float lo, hi; unpack2(acc[i], lo, hi);
            dst[2 * i] = lo; dst[2 * i + 1] = hi;
        }
    }
    __syncthreads();
    if (kh == 0) {
        float o[30];
        const float* src = xs + row * 30;
#pragma unroll
        for (int i = 0; i < 15; i++) {
            float lo, hi; unpack2(acc[i], lo, hi);
            o[2 * i]     = lo + src[2 * i];
            o[2 * i + 1] = hi + src[2 * i + 1];
        }

        const int grow = row0 + row;
        const int b = grow >> 11, n = grow & (Nn - 1);
        const float rs = 0.4472135954999579f;   // 1/sqrt(5)

        float q[10], kk[10], vv[10];
#pragma unroll
        for (int j = 0; j < 10; j++) {
            q[j]  = (o[j]      + bq[j]) * rs;
            kk[j] = (o[j + 10] + bk[j]);
            vv[j] = (o[j + 20] + bv[j]);
        }
#pragma unroll
        for (int h = 0; h < 2; h++) {
            int bh = b * NH + h;
            float* qp = g_Q[bh][n];
            float* kp = g_K[bh][n];
            float* vp = g_V[bh][n];
            *reinterpret_cast<float4*>(qp) = make_float4(q[h*5+0], q[h*5+1], q[h*5+2], q[h*5+3]);
            qp[4] = q[h*5+4];
            *reinterpret_cast<float4*>(kp) = make_float4(kk[h*5+0], kk[h*5+1], kk[h*5+2], kk[h*5+3]);
            kp[4] = kk[h*5+4];
            *reinterpret_cast<float4*>(vp) = make_float4(vv[h*5+0], vv[h*5+1], vv[h*5+2], vv[h*5+3]);
            vp[4] = vv[h*5+4];
        }
    }
}

// =====================================================================
// Kernel 2: streaming causal attention, key range split across 2 blocks.
// Grid (16 qtiles, 32 bh, 2 khalf); partial (sum eV, sum e) to g_A.
// sin in [-1,1] => weight = exp(sin(.)), no running max needed.
// K/V smem transposed so LDS.64 yields packed key-pairs; f32x2 FFMA.
// Next tile's gmem loads are prefetched into registers before compute.
// =====================================================================
#define TK 128

template <bool DIAG>
__device__ __forceinline__ void attn_tile(
    const float* __restrict__ sK, const float* __restrict__ sV,
    const ull* __restrict__ q2, int lim,
    ull acc2[5], ull& den2)
{
    const ull* K2 = reinterpret_cast<const ull*>(sK);   // [d*64 + p]
    const ull* V2 = reinterpret_cast<const ull*>(sV);
#pragma unroll 8
    for (int p = 0; p < TK / 2; p++) {
        ull s2 = mul2(q2[4], K2[4 * 64 + p]);
        fma2(s2, q2[0], K2[0 * 64 + p]);
        fma2(s2, q2[1], K2[1 * 64 + p]);
        fma2(s2, q2[2], K2[2 * 64 + p]);
        fma2(s2, q2[3], K2[3 * 64 + p]);
        float s0, s1; unpack2(s2, s0, s1);
        float e0 = __expf(__sinf(s0));
        float e1 = __expf(__sinf(s1));
        if (DIAG) {
            e0 = (2 * p     <= lim) ? e0 : 0.f;
            e1 = (2 * p + 1 <= lim) ? e1 : 0.f;
        }
        ull e2 = pack2(e0, e1);
        add2(den2, e2);
        fma2(acc2[0], e2, V2[0 * 64 + p]);
        fma2(acc2[1], e2, V2[1 * 64 + p]);
        fma2(acc2[2], e2, V2[2 * 64 + p]);
        fma2(acc2[3], e2, V2[3 * 64 + p]);
        fma2(acc2[4], e2, V2[4 * 64 + p]);
    }
}

__global__ __launch_bounds__(128) void attn_kernel()
{
    __shared__ __align__(16) float sK[5 * TK];
    __shared__ __align__(16) float sV[5 * TK];

    const int tid = threadIdx.x;
    const int qt  = (gridDim.x - 1) - blockIdx.x;   // heavy tiles first
    const int bh  = blockIdx.y;
    const int kh  = blockIdx.z;
    const int qi  = qt * TK + tid;

    const int ntiles = qt + 1;
    const int mid = (ntiles + 1) >> 1;
    const int t0 = kh ? mid : 0;
    const int t1 = kh ? ntiles : mid;

    ull acc2[5] = {0ull, 0ull, 0ull, 0ull, 0ull};
    ull den2 = 0ull;

    if (t0 < t1) {
        const float* qp = g_Q[bh][qi];
        float4 qv = *reinterpret_cast<const float4*>(qp);
        float  q4 = qp[4];
        ull q2[5];
        q2[0] = pack2(qv.x, qv.x); q2[1] = pack2(qv.y, qv.y);
        q2[2] = pack2(qv.z, qv.z); q2[3] = pack2(qv.w, qv.w);
        q2[4] = pack2(q4, q4);

        // prefetch first tile
        float4 ka, va; float k4, v4;
        {
            const int j = t0 * TK + tid;
            ka = *reinterpret_cast<const float4*>(g_K[bh][j]);
            k4 = g_K[bh][j][4];
            va = *reinterpret_cast<const float4*>(g_V[bh][j]);
            v4 = g_V[bh][j][4];
        }

        for (int kt = t0; kt < t1; kt++) {
            __syncthreads();
            sK[0 * TK + tid] = ka.x; sK[1 * TK + tid] = ka.y;
            sK[2 * TK + tid] = ka.z; sK[3 * TK + tid] = ka.w;
            sK[4 * TK + tid] = k4;
            sV[0 * TK + tid] = va.x; sV[1 * TK + tid] = va.y;
            sV[2 * TK + tid] = va.z; sV[3 * TK + tid] = va.w;
            sV[4 * TK + tid] = v4;
            __syncthreads();

            if (kt + 1 < t1) {   // prefetch next tile while computing
                const int j = (kt + 1) * TK + tid;
                ka = *reinterpret_cast<const float4*>(g_K[bh][j]);
                k4 = g_K[bh][j][4];
                va = *reinterpret_cast<const float4*>(g_V[bh][j]);
                v4 = g_V[bh][j][4];
            }

            if (kt == qt) attn_tile<true >(sK, sV, q2, tid, acc2, den2);
            else          attn_tile<false>(sK, sV, q2, 0,   acc2, den2);
        }
    }

    // write partials (even if empty: zeros keep combine simple)
    float a[5], den = 0.f;
#pragma unroll
    for (int d = 0; d < 5; d++) {
        float lo, hi; unpack2(acc2[d], lo, hi);
        a[d] = lo + hi;
    }
    { float dl, dh; unpack2(den2, dl, dh); den = dl + dh; }
    float* op = g_A[bh][qi][kh];
    *reinterpret_cast<float4*>(op) = make_float4(a[0], a[1], a[2], a[3]);
    op[4] = a[4];
    op[5] = den;
}

// =====================================================================
// Kernel 3: combine attention partials + MLP head.
// 256 threads / 32 rows per block; Wm2 (40KB) in smem; f32x2 packed.
// =====================================================================
#define MR 32

__global__ __launch_bounds__(256) void mlp_kernel(
    const float* __restrict__ Wm1, const float* __restrict__ bm1,
    const float* __restrict__ Wm2, const float* __restrict__ bm2,
    float* __restrict__ out)
{
    __shared__ __align__(16) float w2s[HID * DOUT];  // 40 KB
    __shared__ __align__(16) float h1s[MR * HID];
    __shared__ float cs[MR * DK];

    const int tid  = threadIdx.x;
    const int row0 = blockIdx.x * MR;

    for (int e = tid; e < HID * DOUT / 4; e += 256)
        reinterpret_cast<float4*>(w2s)[e] = reinterpret_cast<const float4*>(Wm2)[e];

    // combine attention partials -> concat c[10] per row
    for (int e = tid; e < MR * DK; e += 256) {
        int r = e / DK, k = e % DK;
        int h = k / DH, d = k % DH;
        int grow = row0 + r;
        int b = grow >> 11, n = grow & (Nn - 1);
        const float* A = g_A[b * NH + h][n][0];   // [2][8] contiguous
        float den = A[5] + A[13];
        cs[e] = (A[d] + A[8 + d]) * __fdividef(1.f, den);
    }
    __syncthreads();

    // h1 = leaky_relu(c @ Wm1 + bm1)
    for (int e = tid; e < MR * HID; e += 256) {
        int r = e / HID, j = e % HID;
        const float* crow = cs + r * DK;
        float s = bm1[j];
#pragma unroll
        for (int k = 0; k < DK; k++)
            s = fmaf(crow[k], Wm1[k * HID + j], s);
        h1s[e] = (s > 0.f) ? s : 0.01f * s;
    }
    __syncthreads();

    const int r  = tid >> 3;
    const int cg = tid & 7;
    ull h2[HID];
#pragma unroll
    for (int k = 0; k < HID; k++) {
        float hk = h1s[r * HID + k];
        h2[k] = pack2(hk, hk);
    }

    float* orow = out + (size_t)(row0 + r) * DOUT;
#pragma unroll 2
    for (int c4 = cg; c4 < DOUT / 4; c4 += 8) {
        union { float4 f; ull u[2]; } a;
        a.f = reinterpret_cast<const float4*>(bm2)[c4];
#pragma unroll
        for (int k = 0; k < HID; k++) {
            union { float4 f; ull u[2]; } w;
            w.f = *reinterpret_cast<const float4*>(w2s + k * DOUT + c4 * 4);
            fma2(a.u[0], h2[k], w.u[0]);
            fma2(a.u[1], h2[k], w.u[1]);
        }
        reinterpret_cast<float4*>(orow)[c4] = a.f;
    }
}

// =====================================================================
extern "C" void kernel_launch(void* const* d_in, const int* in_sizes, int n_in,
                              void* d_out, int out_size)
{
    const float* x   = (const float*)d_in[0];
    const float* Wq  = (const float*)d_in[1];
    const float* bq  = (const float*)d_in[2];
    const float* Wk  = (const float*)d_in[3];
    const float* bk  = (const float*)d_in[4];
    const float* Wv  = (const float*)d_in[5];
    const float* bv  = (const float*)d_in[6];
    const float* Wm1 = (const float*)d_in[7];
    const float* bm1 = (const float*)d_in[8];
    const float* Wm2 = (const float*)d_in[9];
    const float* bm2 = (const float*)d_in[10];

    proj_kernel<<<ROWS / PR, 256>>>(x, Wq, bq, Wk, bk, Wv, bv);
    attn_kernel<<<dim3(Nn / TK, BH, 2), 128>>>();
    mlp_kernel<<<ROWS / MR, 256>>>(Wm1, bm1, Wm2, bm2, (float*)d_out);
}